// round 13
// baseline (speedup 1.0000x reference)
#include <cuda_runtime.h>

// BiLingual dual EmbeddingBag(sum)
//   inputs_pri: int32 [4096, 200]
//   inputs_sec: int32 [4096, 200]
//   emb_pri:    f32   [100000, 64]   (rows 256B)
//   emb_sec:    f32   [100000, 64]
//   out:        f32   [2, 4096, 64]
//
// Champion structure (R2, 25.1us): one warp per bag, half-warp h loads token
// j+h as float4 (one LDG.128 covers 2 tokens), indices staged in smem,
// unroll 4, plain __ldg (L1-allocating — L1 hits carry ~1/3 of traffic).
// R6 change vs champion: WPB=2 (64-thread blocks, 4096 blocks) to cut
// multi-CTA spread / tail imbalance. (evict_last dropped: ptxas rejects it
// on 16B loads for sm_103a.)

#define EB_B 4096
#define EB_S 200
#define EB_D 64
#define WPB 2
#define NBLK_PER_TAB (EB_B / WPB)   // 2048

__global__ __launch_bounds__(WPB * 32)
void embed_sum_kernel(const int* __restrict__ idx_pri,
                      const int* __restrict__ idx_sec,
                      const float* __restrict__ emb_pri,
                      const float* __restrict__ emb_sec,
                      float* __restrict__ out) {
    __shared__ int sidx[WPB * EB_S];

    const int tid  = threadIdx.x;
    const int warp = tid >> 5;
    const int lane = tid & 31;
    const int half = lane >> 4;     // which token of the pair
    const int hl   = lane & 15;     // dim quad within row

    const int*    idx;
    const float4* tab;
    int           row_base;
    if (blockIdx.x < NBLK_PER_TAB) {
        idx      = idx_pri;
        tab      = reinterpret_cast<const float4*>(emb_pri);
        row_base = blockIdx.x * WPB;
    } else {
        idx      = idx_sec;
        tab      = reinterpret_cast<const float4*>(emb_sec);
        row_base = (blockIdx.x - NBLK_PER_TAB) * WPB;
    }

    // Stage this block's 2x200 indices (coalesced).
    {
        const int* gsrc = idx + row_base * EB_S;
        for (int i = tid; i < WPB * EB_S; i += WPB * 32)
            sidx[i] = gsrc[i];
    }
    __syncthreads();

    const int* my = &sidx[warp * EB_S];

    float4 acc = make_float4(0.f, 0.f, 0.f, 0.f);

    // 100 pair-iterations, unroll 4 -> 4 LDG.128 in flight.
    #pragma unroll 4
    for (int j = 0; j < EB_S; j += 2) {
        const int id = my[j + half];
        const float4 v = __ldg(&tab[id * (EB_D / 4) + hl]);
        acc.x += v.x;
        acc.y += v.y;
        acc.z += v.z;
        acc.w += v.w;
    }

    // Combine the two half-warp partials (same bag, same dim quad).
    acc.x += __shfl_xor_sync(0xffffffffu, acc.x, 16);
    acc.y += __shfl_xor_sync(0xffffffffu, acc.y, 16);
    acc.z += __shfl_xor_sync(0xffffffffu, acc.z, 16);
    acc.w += __shfl_xor_sync(0xffffffffu, acc.w, 16);

    if (half == 0) {
        const int out_row =
            (blockIdx.x < NBLK_PER_TAB ? 0 : EB_B) + row_base + warp;
        reinterpret_cast<float4*>(out)[out_row * (EB_D / 4) + hl] = acc;
    }
}

extern "C" void kernel_launch(void* const* d_in, const int* in_sizes, int n_in,
                              void* d_out, int out_size) {
    const int*   idx_pri = (const int*)d_in[0];
    const int*   idx_sec = (const int*)d_in[1];
    const float* emb_pri = (const float*)d_in[2];
    const float* emb_sec = (const float*)d_in[3];
    float* outp = (float*)d_out;

    embed_sum_kernel<<<2 * NBLK_PER_TAB, WPB * 32>>>(
        idx_pri, idx_sec, emb_pri, emb_sec, outp);
}